// round 17
// baseline (speedup 1.0000x reference)
#include <cuda_runtime.h>
#include <cuda_bf16.h>
#include <math.h>
#include <stdint.h>

constexpr int H = 256;
constexpr int B = 4;
constexpr int S = 128;
constexpr int T = 128;

typedef unsigned long long ull;

// Scratch (device globals — no allocation allowed)
__device__ float g_pre_x[(size_t)B * S * T * H];
__device__ float g_pre_y[(size_t)B * S * T * H];
__device__ float g_hx  [(size_t)B * S * T * H];
__device__ float g_hy  [(size_t)B * S * T * H];
__device__ float g_psx [(size_t)B * S * H];
__device__ float g_psy [(size_t)B * T * H];
// bf16 hi/lo splits of the 3-depth ih-weights (x and y paths)
__device__ __nv_bfloat16 g_wxh[3 * 256 * 256];
__device__ __nv_bfloat16 g_wxl[3 * 256 * 256];
__device__ __nv_bfloat16 g_wyh[3 * 256 * 256];
__device__ __nv_bfloat16 g_wyl[3 * 256 * 256];

// ---------------- PTX helpers ----------------
__device__ __forceinline__ uint32_t smem_u32(const void* p) {
    uint32_t a;
    asm("{ .reg .u64 t; cvta.to.shared.u64 t, %1; cvt.u32.u64 %0, t; }" : "=r"(a) : "l"(p));
    return a;
}
__device__ __forceinline__ uint32_t mapa_u32(uint32_t addr, uint32_t rank) {
    uint32_t r;
    asm("mapa.shared::cluster.u32 %0, %1, %2;" : "=r"(r) : "r"(addr), "r"(rank));
    return r;
}
__device__ __forceinline__ void st_cluster_b32(uint32_t addr, uint32_t v) {
    asm volatile("st.shared::cluster.b32 [%0], %1;" :: "r"(addr), "r"(v) : "memory");
}
#define CLUSTER_ARRIVE() asm volatile("barrier.cluster.arrive.aligned;" ::: "memory")
#define CLUSTER_WAIT()   asm volatile("barrier.cluster.wait.aligned;" ::: "memory")

// Accurate-enough fast tanh (MUFU path forced; err ~1e-6, budget 1e-3)
__device__ __forceinline__ float my_tanh(float x) {
    float ax = fabsf(x);
    float e  = __expf(-2.0f * ax);
    float t  = __fdividef(1.0f - e, 1.0f + e);
    return x < 0.0f ? -t : t;
}

// bf16 MMA m16n8k16, fp32 accumulate (sm_80-era HMMA — compiles on compute_103)
__device__ __forceinline__ void mma_bf16(float* c, const uint32_t* a, const uint32_t* b) {
    asm volatile(
        "mma.sync.aligned.m16n8k16.row.col.f32.bf16.bf16.f32 "
        "{%0,%1,%2,%3}, {%4,%5,%6,%7}, {%8,%9}, {%0,%1,%2,%3};"
        : "+f"(c[0]), "+f"(c[1]), "+f"(c[2]), "+f"(c[3])
        : "r"(a[0]), "r"(a[1]), "r"(a[2]), "r"(a[3]), "r"(b[0]), "r"(b[1]));
}

__device__ __forceinline__ uint32_t pack_bf16x2(float a, float b) {
    return ((uint32_t)__bfloat16_as_ushort(__float2bfloat16_rn(b)) << 16)
         | __bfloat16_as_ushort(__float2bfloat16_rn(a));
}

// ---------------------------------------------------------------------------
// W split kernel: fp32 -> (hi, lo) bf16 pair.  lo = bf16(v - float(hi)).
// ---------------------------------------------------------------------------
__global__ void conv_w(const float* __restrict__ W,
                       __nv_bfloat16* __restrict__ hi,
                       __nv_bfloat16* __restrict__ lo, int n)
{
    int i = blockIdx.x * 256 + threadIdx.x;
    if (i < n) {
        float v = W[i];
        __nv_bfloat16 h = __float2bfloat16_rn(v);
        hi[i] = h;
        lo[i] = __float2bfloat16_rn(v - __bfloat162float(h));
    }
}

// ---------------------------------------------------------------------------
// HMMA prepass (UNCHANGED from R14, passing): C = A W^T + b1 + b2, bf16x3.
// ---------------------------------------------------------------------------
constexpr int PSTR = 40;   // smem row stride in bf16

__global__ void __launch_bounds__(256, 1) hmma_prepass(
    const float* __restrict__ A,
    const __nv_bfloat16* __restrict__ Whi, const __nv_bfloat16* __restrict__ Wlo,
    const float* __restrict__ b1, const float* __restrict__ b2,
    float* __restrict__ C)
{
    __shared__ __nv_bfloat16 Ah[128 * PSTR], Al[128 * PSTR];
    __shared__ __nv_bfloat16 Wh[128 * PSTR], Wl[128 * PSTR];
    __shared__ float bs[128];

    const int m0  = blockIdx.x << 7;
    const int n0  = blockIdx.y << 7;
    const int tid = threadIdx.x;
    const int wid = tid >> 5;
    const int lane = tid & 31;
    const int gid = lane >> 2;
    const int tg  = lane & 3;
    const int wm  = wid >> 2;
    const int wn  = wid & 3;

    if (tid < 128) bs[tid] = b1[n0 + tid] + b2[n0 + tid];

    const int srow = tid >> 1;
    const int shalf = (tid & 1) << 4;
    const float* Ag = A + (size_t)(m0 + srow) * H + shalf;
    const __nv_bfloat16* WhG = Whi + (size_t)(n0 + srow) * H + shalf;
    const __nv_bfloat16* WlG = Wlo + (size_t)(n0 + srow) * H + shalf;

    float4 pa[4];
    uint4  pwh[2], pwl[2];
    #pragma unroll
    for (int q = 0; q < 4; q++) pa[q] = *(const float4*)(Ag + q * 4);
    #pragma unroll
    for (int q = 0; q < 2; q++) {
        pwh[q] = *(const uint4*)(WhG + q * 8);
        pwl[q] = *(const uint4*)(WlG + q * 8);
    }

    float acc[4][4][4] = {};

    for (int kc = 0; kc < 8; kc++) {
        #pragma unroll
        for (int q = 0; q < 4; q++) {
            float4 v = pa[q];
            __nv_bfloat16 h0 = __float2bfloat16_rn(v.x);
            __nv_bfloat16 h1 = __float2bfloat16_rn(v.y);
            __nv_bfloat16 h2 = __float2bfloat16_rn(v.z);
            __nv_bfloat16 h3 = __float2bfloat16_rn(v.w);
            uint2 uh, ul;
            uh.x = ((uint32_t)__bfloat16_as_ushort(h1) << 16) | __bfloat16_as_ushort(h0);
            uh.y = ((uint32_t)__bfloat16_as_ushort(h3) << 16) | __bfloat16_as_ushort(h2);
            __nv_bfloat16 l0 = __float2bfloat16_rn(v.x - __bfloat162float(h0));
            __nv_bfloat16 l1 = __float2bfloat16_rn(v.y - __bfloat162float(h1));
            __nv_bfloat16 l2 = __float2bfloat16_rn(v.z - __bfloat162float(h2));
            __nv_bfloat16 l3 = __float2bfloat16_rn(v.w - __bfloat162float(h3));
            ul.x = ((uint32_t)__bfloat16_as_ushort(l1) << 16) | __bfloat16_as_ushort(l0);
            ul.y = ((uint32_t)__bfloat16_as_ushort(l3) << 16) | __bfloat16_as_ushort(l2);
            *(uint2*)&Ah[srow * PSTR + shalf + q * 4] = uh;
            *(uint2*)&Al[srow * PSTR + shalf + q * 4] = ul;
        }
        #pragma unroll
        for (int q = 0; q < 2; q++) {
            *(uint4*)&Wh[srow * PSTR + shalf + q * 8] = pwh[q];
            *(uint4*)&Wl[srow * PSTR + shalf + q * 8] = pwl[q];
        }
        __syncthreads();

        if (kc < 7) {
            const int kb = (kc + 1) << 5;
            #pragma unroll
            for (int q = 0; q < 4; q++) pa[q] = *(const float4*)(Ag + kb + q * 4);
            #pragma unroll
            for (int q = 0; q < 2; q++) {
                pwh[q] = *(const uint4*)(WhG + kb + q * 8);
                pwl[q] = *(const uint4*)(WlG + kb + q * 8);
            }
        }

        #pragma unroll
        for (int ks = 0; ks < 32; ks += 16) {
            uint32_t ah[4][4], al[4][4], wh[4][2], wl[4][2];
            #pragma unroll
            for (int fm = 0; fm < 4; fm++) {
                const int r0 = ((wm << 6) + (fm << 4) + gid) * PSTR + ks + (tg << 1);
                ah[fm][0] = *(const uint32_t*)&Ah[r0];
                ah[fm][1] = *(const uint32_t*)&Ah[r0 + 8 * PSTR];
                ah[fm][2] = *(const uint32_t*)&Ah[r0 + 8];
                ah[fm][3] = *(const uint32_t*)&Ah[r0 + 8 * PSTR + 8];
                al[fm][0] = *(const uint32_t*)&Al[r0];
                al[fm][1] = *(const uint32_t*)&Al[r0 + 8 * PSTR];
                al[fm][2] = *(const uint32_t*)&Al[r0 + 8];
                al[fm][3] = *(const uint32_t*)&Al[r0 + 8 * PSTR + 8];
            }
            #pragma unroll
            for (int fn = 0; fn < 4; fn++) {
                const int nb = ((wn << 5) + (fn << 3) + gid) * PSTR + ks + (tg << 1);
                wh[fn][0] = *(const uint32_t*)&Wh[nb];
                wh[fn][1] = *(const uint32_t*)&Wh[nb + 8];
                wl[fn][0] = *(const uint32_t*)&Wl[nb];
                wl[fn][1] = *(const uint32_t*)&Wl[nb + 8];
            }
            #pragma unroll
            for (int fm = 0; fm < 4; fm++)
                #pragma unroll
                for (int fn = 0; fn < 4; fn++) {
                    mma_bf16(acc[fm][fn], ah[fm], wh[fn]);
                    mma_bf16(acc[fm][fn], ah[fm], wl[fn]);
                    mma_bf16(acc[fm][fn], al[fm], wh[fn]);
                }
        }
        __syncthreads();
    }

    #pragma unroll
    for (int fm = 0; fm < 4; fm++) {
        const int row = m0 + (wm << 6) + (fm << 4) + gid;
        #pragma unroll
        for (int fn = 0; fn < 4; fn++) {
            const int colL = (wn << 5) + (fn << 3) + (tg << 1);
            const float2 bv = *(const float2*)&bs[colL];
            const float* c = acc[fm][fn];
            float* Cp = C + (size_t)row * H + n0 + colL;
            *(float2*)Cp = make_float2(c[0] + bv.x, c[1] + bv.y);
            *(float2*)(Cp + 8 * H) = make_float2(c[2] + bv.x, c[3] + bv.y);
        }
    }
}

// ---------------------------------------------------------------------------
// HMMA recurrence v4 = R14's proven recur4 (barrier.cluster split arrive/wait)
// + 3-way split accumulators (6 independent HMMA chains per thread)
// + peer-DSMEM-first publish ordering.
// grid (2, 64), cluster (2,1,1), 256 threads (8 warps, n16 each).
// ---------------------------------------------------------------------------
struct RP {
    const float* W;
    const float* pre; long p_sb, p_sstep, p_sj;
    float*       out; long o_sb, o_sstep, o_sj;
    int diag;
};

constexpr int WSTR = 264;                             // bf16 row stride
constexpr int OFF_WL  = 128 * WSTR * 2;               // 67584
constexpr int OFF_AH0 = 2 * OFF_WL;                   // 135168
constexpr int APLANE  = 16 * WSTR * 2;                // 8448
constexpr int OFF_AL0 = OFF_AH0 + APLANE;
constexpr int OFF_AH1 = OFF_AL0 + APLANE;
constexpr int OFF_AL1 = OFF_AH1 + APLANE;
constexpr int RECUR_SMEM = OFF_AL1 + APLANE;          // 168960 B

__global__ void __launch_bounds__(256, 1) __cluster_dims__(2, 1, 1)
recur6(RP X, RP Y)
{
    extern __shared__ char smx[];
    __nv_bfloat16* Wh = (__nv_bfloat16*)(smx);
    __nv_bfloat16* Wl = (__nv_bfloat16*)(smx + OFF_WL);
    __nv_bfloat16* AhB[2] = { (__nv_bfloat16*)(smx + OFF_AH0),
                              (__nv_bfloat16*)(smx + OFF_AH1) };
    __nv_bfloat16* AlB[2] = { (__nv_bfloat16*)(smx + OFF_AL0),
                              (__nv_bfloat16*)(smx + OFF_AL1) };
    const uint32_t planeH[2] = { OFF_AH0, OFF_AH1 };
    const uint32_t planeL[2] = { OFF_AL0, OFF_AL1 };

    const int rank  = blockIdx.x;
    const int clid  = blockIdx.y;
    const int path  = clid >> 5;
    const RP  P     = path ? Y : X;
    const int grp   = clid & 31;
    const int b     = grp >> 3;
    const int dbase = (grp & 7) << 4;

    const int tid  = threadIdx.x;
    const int wid  = tid >> 5;          // warp 0..7, n16 each
    const int lane = tid & 31;
    const int gid  = lane >> 2;
    const int tg   = lane & 3;

    // ---- fill W_hh hi/lo SMEM (rows = local cols of this rank) ----
    {
        const float* Wg = P.W + (size_t)(rank << 7) * H;
        for (int idx = tid; idx < 128 * 64; idx += 256) {
            int n = idx >> 6, kq = (idx & 63) << 2;
            float4 v = *(const float4*)&Wg[(size_t)n * H + kq];
            __nv_bfloat16 h0 = __float2bfloat16_rn(v.x);
            __nv_bfloat16 h1 = __float2bfloat16_rn(v.y);
            __nv_bfloat16 h2 = __float2bfloat16_rn(v.z);
            __nv_bfloat16 h3 = __float2bfloat16_rn(v.w);
            uint2 uh, ul;
            uh.x = ((uint32_t)__bfloat16_as_ushort(h1) << 16) | __bfloat16_as_ushort(h0);
            uh.y = ((uint32_t)__bfloat16_as_ushort(h3) << 16) | __bfloat16_as_ushort(h2);
            ul.x = ((uint32_t)__bfloat16_as_ushort(
                        __float2bfloat16_rn(v.y - __bfloat162float(h1))) << 16)
                 | __bfloat16_as_ushort(__float2bfloat16_rn(v.x - __bfloat162float(h0)));
            ul.y = ((uint32_t)__bfloat16_as_ushort(
                        __float2bfloat16_rn(v.w - __bfloat162float(h3))) << 16)
                 | __bfloat16_as_ushort(__float2bfloat16_rn(v.z - __bfloat162float(h2)));
            *(uint2*)&Wh[n * WSTR + kq] = uh;
            *(uint2*)&Wl[n * WSTR + kq] = ul;
        }
    }

    const uint32_t peerBase = mapa_u32(smem_u32(smx), rank ^ 1);

    const int gc0 = (rank << 7) + (wid << 4) + (tg << 1);
    int jc0 = dbase + gid;
    int jc1 = dbase + gid + 8;

    float2 pv[2][2];
    #pragma unroll
    for (int f = 0; f < 2; f++) {
        pv[0][f] = *(const float2*)(P.pre + b * P.p_sb + jc0 * P.p_sj + gc0 + (f << 3));
        pv[1][f] = *(const float2*)(P.pre + b * P.p_sb + jc1 * P.p_sj + gc0 + (f << 3));
    }

    const int kOwn  = rank << 3;          // own-half k-steps (8 of 16)
    const int kPeer = (rank ^ 1) << 3;
    const int aoff  = gid * WSTR + (tg << 1);

    __syncthreads();   // W SMEM ready

    // ---- hoist W fragments to registers (own-half-first ordering) ----
    uint32_t wfr[2][16][4];
    #pragma unroll
    for (int half = 0; half < 2; half++) {
        const int kb = half ? kPeer : kOwn;
        #pragma unroll
        for (int s = 0; s < 8; s++) {
            const int kk = (kb + s) << 4;
            #pragma unroll
            for (int f = 0; f < 2; f++) {
                const int nrow = (wid << 4) + (f << 3) + gid;
                const __nv_bfloat16* wp = Wh + nrow * WSTR + (tg << 1) + kk;
                const __nv_bfloat16* lp = Wl + nrow * WSTR + (tg << 1) + kk;
                wfr[f][half * 8 + s][0] = *(const uint32_t*)wp;
                wfr[f][half * 8 + s][1] = *(const uint32_t*)(wp + 8);
                wfr[f][half * 8 + s][2] = *(const uint32_t*)lp;
                wfr[f][half * 8 + s][3] = *(const uint32_t*)(lp + 8);
            }
        }
    }

    for (int st = 0; st < 128; st++) {
        // 3-way split accumulators -> 6 independent HMMA chains per thread
        float accA[2][4] = {};   // ah*wh
        float accB[2][4] = {};   // ah*wl
        float accC[2][4] = {};   // al*wh

        if (st > 0) {
            const int rd = st & 1;
            const __nv_bfloat16* Ach = AhB[rd];
            const __nv_bfloat16* Acl = AlB[rd];
            #pragma unroll
            for (int half = 0; half < 2; half++) {
                const int kb = half ? kPeer : kOwn;
                if (half) CLUSTER_WAIT();             // peer half now visible
                #pragma unroll
                for (int s = 0; s < 8; s++) {
                    const int kk = (kb + s) << 4;
                    const __nv_bfloat16* ap  = Ach + aoff + kk;
                    const __nv_bfloat16* alp = Acl + aoff + kk;
                    uint32_t ah[4], al[4];
                    ah[0] = *(const uint32_t*)ap;
                    ah[1] = *(const uint32_t*)(ap + 8 * WSTR);
                    ah[2] = *(const uint32_t*)(ap + 8);
                    ah[3] = *(const uint32_t*)(ap + 8 * WSTR + 8);
                    al[0] = *(const uint32_t*)alp;
                    al[1] = *(const uint32_t*)(alp + 8 * WSTR);
                    al[2] = *(const uint32_t*)(alp + 8);
                    al[3] = *(const uint32_t*)(alp + 8 * WSTR + 8);
                    #pragma unroll
                    for (int f = 0; f < 2; f++) {
                        const uint32_t* wq = wfr[f][half * 8 + s];
                        mma_bf16(accA[f], ah, wq);
                        mma_bf16(accB[f], ah, wq + 2);
                        mma_bf16(accC[f], al, wq);
                    }
                }
            }
        }

        float h0[2][2], h1[2][2];
        #pragma unroll
        for (int f = 0; f < 2; f++) {
            h0[f][0] = my_tanh((accA[f][0] + accB[f][0]) + accC[f][0] + pv[0][f].x);
            h0[f][1] = my_tanh((accA[f][1] + accB[f][1]) + accC[f][1] + pv[0][f].y);
            h1[f][0] = my_tanh((accA[f][2] + accB[f][2]) + accC[f][2] + pv[1][f].x);
            h1[f][1] = my_tanh((accA[f][3] + accB[f][3]) + accC[f][3] + pv[1][f].y);
        }

        if (st < 127) {
            // publish state h(st): peer DSMEM first (peer critical path), then own
            const int wbuf = (st & 1) ^ 1;
            __nv_bfloat16* Anh = AhB[wbuf];
            __nv_bfloat16* Anl = AlB[wbuf];
            const uint32_t pH = peerBase + planeH[wbuf];
            const uint32_t pL = peerBase + planeL[wbuf];
            #pragma unroll
            for (int f = 0; f < 2; f++) {
                const int gcf = gc0 + (f << 3);
                const int o0 = gid * WSTR + gcf;
                const int o1 = (gid + 8) * WSTR + gcf;
                uint32_t hi0 = pack_bf16x2(h0[f][0], h0[f][1]);
                uint32_t hi1 = pack_bf16x2(h1[f][0], h1[f][1]);
                float r00 = h0[f][0] - __bfloat162float(__float2bfloat16_rn(h0[f][0]));
                float r01 = h0[f][1] - __bfloat162float(__float2bfloat16_rn(h0[f][1]));
                float r10 = h1[f][0] - __bfloat162float(__float2bfloat16_rn(h1[f][0]));
                float r11 = h1[f][1] - __bfloat162float(__float2bfloat16_rn(h1[f][1]));
                uint32_t lo0 = pack_bf16x2(r00, r01);
                uint32_t lo1 = pack_bf16x2(r10, r11);
                st_cluster_b32(pH + (uint32_t)o0 * 2, hi0);
                st_cluster_b32(pH + (uint32_t)o1 * 2, hi1);
                st_cluster_b32(pL + (uint32_t)o0 * 2, lo0);
                st_cluster_b32(pL + (uint32_t)o1 * 2, lo1);
                *(uint32_t*)&Anh[o0] = hi0;  *(uint32_t*)&Anh[o1] = hi1;
                *(uint32_t*)&Anl[o0] = lo0;  *(uint32_t*)&Anl[o1] = lo1;
            }
            __syncthreads();       // own stores visible CTA-wide (own-half read)
            CLUSTER_ARRIVE();      // releases DSMEM stores; matched by wait(st+1)
        }

        // global output (fp32) inside the arrive->wait window
        #pragma unroll
        for (int f = 0; f < 2; f++) {
            const int gcf = gc0 + (f << 3);
            float* op0 = P.out + b * P.o_sb + st * P.o_sstep + jc0 * P.o_sj + gcf;
            float* op1 = P.out + b * P.o_sb + st * P.o_sstep + jc1 * P.o_sj + gcf;
            *(float2*)op0 = make_float2(h0[f][0], h0[f][1]);
            *(float2*)op1 = make_float2(h1[f][0], h1[f][1]);
        }

        if (st < 127) {
            if (P.diag) { jc0 = (jc0 + 1) & 127; jc1 = (jc1 + 1) & 127; }
            #pragma unroll
            for (int f = 0; f < 2; f++) {
                pv[0][f] = *(const float2*)(P.pre + b * P.p_sb + (st + 1) * P.p_sstep
                                            + jc0 * P.p_sj + gc0 + (f << 3));
                pv[1][f] = *(const float2*)(P.pre + b * P.p_sb + (st + 1) * P.p_sstep
                                            + jc1 * P.p_sj + gc0 + (f << 3));
            }
        }
    }
}

// ---------------------------------------------------------------------------
// Host orchestration: 2 W-split + 3 x (2 prepass + 1 recurrence) launches.
// ---------------------------------------------------------------------------
extern "C" void kernel_launch(void* const* d_in, const int* in_sizes, int n_in,
                              void* d_out, int out_size)
{
    const float* src   = (const float*)d_in[0];
    const float* trg   = (const float*)d_in[1];
    const float* Wx_ih = (const float*)d_in[2];
    const float* Wx_hh = (const float*)d_in[3];
    const float* bx_ih = (const float*)d_in[4];
    const float* bx_hh = (const float*)d_in[5];
    const float* Wy_ih = (const float*)d_in[6];
    const float* Wy_hh = (const float*)d_in[7];
    const float* by_ih = (const float*)d_in[8];
    const float* by_hh = (const float*)d_in[9];
    float* out = (float*)d_out;

    float *pre_x, *pre_y, *hx, *hy, *psx, *psy;
    __nv_bfloat16 *wxh, *wxl, *wyh, *wyl;
    cudaGetSymbolAddress((void**)&pre_x, g_pre_x);
    cudaGetSymbolAddress((void**)&pre_y, g_pre_y);
    cudaGetSymbolAddress((void**)&hx,    g_hx);
    cudaGetSymbolAddress((void**)&hy,    g_hy);
    cudaGetSymbolAddress((void**)&psx,   g_psx);
    cudaGetSymbolAddress((void**)&psy,   g_psy);
    cudaGetSymbolAddress((void**)&wxh,   g_wxh);
    cudaGetSymbolAddress((void**)&wxl,   g_wxl);
    cudaGetSymbolAddress((void**)&wyh,   g_wyh);
    cudaGetSymbolAddress((void**)&wyl,   g_wyl);

    cudaFuncSetAttribute(recur6,
                         cudaFuncAttributeMaxDynamicSharedMemorySize, RECUR_SMEM);

    const int nW = 3 * 256 * 256;
    conv_w<<<(nW + 255) / 256, 256>>>(Wx_ih, wxh, wxl, nW);
    conv_w<<<(nW + 255) / 256, 256>>>(Wy_ih, wyh, wyl, nW);

    for (int d = 0; d < 3; d++) {
        const int woff = d * 256 * 256;
        if (d == 0) {
            hmma_prepass<<<dim3(B * S / 128, 2), 256>>>(
                src, wxh + woff, wxl + woff, bx_ih, bx_hh, psx);
            hmma_prepass<<<dim3(B * T / 128, 2), 256>>>(
                trg, wyh + woff, wyl + woff, by_ih, by_hh, psy);
        } else {
            hmma_prepass<<<dim3(B * S * T / 128, 2), 256>>>(
                hx, wxh + woff, wxl + woff, bx_ih + d * H, bx_hh + d * H, pre_x);
            hmma_prepass<<<dim3(B * S * T / 128, 2), 256>>>(
                hy, wyh + woff, wyl + woff, by_ih + d * H, by_hh + d * H, pre_y);
        }

        const long OS = (d == 2) ? 2 * H : H;
        float* Ox = (d == 2) ? out     : hx;
        float* Oy = (d == 2) ? out + H : hy;

        RP X, Y;
        X.W = Wx_hh + (size_t)d * H * H;  X.diag = 1;
        X.out = Ox; X.o_sb = (long)S * T * OS; X.o_sstep = (long)T * OS; X.o_sj = OS;
        if (d == 0) { X.pre = psx;   X.p_sb = (long)S * H;     X.p_sstep = H;           X.p_sj = 0; }
        else        { X.pre = pre_x; X.p_sb = (long)S * T * H; X.p_sstep = (long)T * H; X.p_sj = H; }

        Y.W = Wy_hh + (size_t)d * H * H;  Y.diag = 0;
        Y.out = Oy; Y.o_sb = (long)S * T * OS; Y.o_sstep = OS; Y.o_sj = (long)T * OS;
        if (d == 0) { Y.pre = psy;   Y.p_sb = (long)T * H;     Y.p_sstep = H; Y.p_sj = 0; }
        else        { Y.pre = pre_y; Y.p_sb = (long)S * T * H; Y.p_sstep = H; Y.p_sj = (long)T * H; }

        recur6<<<dim3(2, 64), 256, RECUR_SMEM>>>(X, Y);
    }
}